// round 6
// baseline (speedup 1.0000x reference)
#include <cuda_runtime.h>
#include <cstdint>

// Problem constants
#define NB   32
#define NS   128
#define NW   4096      // NB*NS independent words
#define CC   32        // chars per word (time steps)
#define HH   256       // hidden
#define G3   768       // 3*H
#define EE   128       // embed dim
#define NV   262       // vocab
#define WPB  16        // words per block
#define HROW 20        // padded smem row for h (16 words + pad, 16B aligned)
#define BLOCKS_PER_DIR (NW / WPB)   // 256

typedef unsigned long long u64;

// Precomputed x-projection table: P[d][v][j] = embed[v].W_ih[d][j] + b_ih[d][j]
// (+ b_hh[j] folded in for the r and z gates, j < 512)
__device__ float g_P[2][NV][G3];
// k-major transposed recurrent weights: g_Wt[d][k][j] = W_hh[d][j][k]
__device__ float g_Wt[2][HH][G3];
// k-major transposed input weights (for coalesced prep_p)
__device__ float g_WtI[2][EE][G3];
// lane-duplicated, k-paired recurrent weights for the f32x2 hot loop:
// g_Wd[d][k2][g][j] = (w, w, w', w') with w = W_hh[g*256+j][2*k2], w' = [2*k2+1]
__device__ float4 g_Wd[2][HH / 2][3][256];

// ---------------------------------------------------------------------------
// Packed fp32x2 helpers (Blackwell 2x-rate fp32; ptxas never auto-emits)
// ---------------------------------------------------------------------------
__device__ __forceinline__ void fma2(u64& d, u64 a, u64 b) {
    asm("fma.rn.f32x2 %0, %1, %2, %3;" : "=l"(d) : "l"(a), "l"(b), "l"(d));
}

// ---------------------------------------------------------------------------
// Prepack 0: transpose W_hh (768x256) and W_ih (768x128) to k-major.
// ---------------------------------------------------------------------------
__global__ void prep_tr_kernel(const float* __restrict__ Whh_fw,
                               const float* __restrict__ Whh_bw,
                               const float* __restrict__ Wih_fw,
                               const float* __restrict__ Wih_bw)
{
    int j = blockIdx.x;
    int d = blockIdx.y;
    int k = threadIdx.x;
    const float* Wh = d ? Whh_bw : Whh_fw;
    const float* Wi = d ? Wih_bw : Wih_fw;
    g_Wt[d][k][j] = Wh[(size_t)j * HH + k];
    if (k < EE) g_WtI[d][k][j] = Wi[(size_t)j * EE + k];
}

// ---------------------------------------------------------------------------
// Prepack 1: lane-duplicated k-paired weight table (from g_Wt, coalesced).
// grid (HH/2, 2), 256 threads.
// ---------------------------------------------------------------------------
__global__ void prep_wd_kernel()
{
    int k2  = blockIdx.x;
    int d   = blockIdx.y;
    int tid = threadIdx.x;
#pragma unroll
    for (int g = 0; g < 3; g++) {
        float a = g_Wt[d][2 * k2][g * 256 + tid];
        float b = g_Wt[d][2 * k2 + 1][g * 256 + tid];
        g_Wd[d][k2][g][tid] = make_float4(a, a, b, b);
    }
}

// ---------------------------------------------------------------------------
// Prepack 2: input-projection table, coalesced via g_WtI.  grid (NV, 2).
// ---------------------------------------------------------------------------
__global__ void prep_p_kernel(const float* __restrict__ embed,
                              const float* __restrict__ bih_fw,
                              const float* __restrict__ bhh_fw,
                              const float* __restrict__ bih_bw,
                              const float* __restrict__ bhh_bw)
{
    int v = blockIdx.x;
    int d = blockIdx.y;
    int tid = threadIdx.x;
    const float* bi = d ? bih_bw : bih_fw;
    const float* bh = d ? bhh_bw : bhh_fw;
    const float* ev = embed + (size_t)v * EE;
    float a0 = 0.f, a1 = 0.f, a2 = 0.f;
#pragma unroll 4
    for (int k = 0; k < EE; k++) {
        float e = __ldg(ev + k);                        // warp-broadcast
        const float* w = &g_WtI[d][k][0];
        a0 = fmaf(e, __ldg(w + tid),       a0);
        a1 = fmaf(e, __ldg(w + tid + 256), a1);
        a2 = fmaf(e, __ldg(w + tid + 512), a2);
    }
    g_P[d][v][tid]       = a0 + bi[tid]       + bh[tid];
    g_P[d][v][tid + 256] = a1 + bi[tid + 256] + bh[tid + 256];
    g_P[d][v][tid + 512] = a2 + bi[tid + 512];          // n-gate: b_hh NOT folded
}

// ---------------------------------------------------------------------------
// Activations
// ---------------------------------------------------------------------------
__device__ __forceinline__ float sigmoid_f(float x) {
    return __fdividef(1.f, 1.f + __expf(-x));
}
__device__ __forceinline__ float tanh_f(float x) {
    x = fmaxf(-15.f, fminf(15.f, x));
    float e = __expf(-2.f * x);
    return __fdividef(1.f - e, 1.f + e);
}

// ---------------------------------------------------------------------------
// Main recurrent kernel (packed fp32x2, pre-duplicated weights).
// Block = 16 words x one direction, 256 threads; thread tid owns the (r,z,n)
// gate triple for hidden index i = tid.  Words packed in pairs into the
// f32x2 lanes; h stored word-major per k (hsm[k][word], row padded to 20)
// so one broadcast LDS.128 feeds two word-pair FFMA2s.  Weights come from
// the pre-duplicated table: one LDG.128 = two ready f32x2 operands (no dup
// movs, 6 LDG.128 per 4k vs 12 LDG.32 + 12 movs before).
// ---------------------------------------------------------------------------
__global__ void __launch_bounds__(256, 2) gru_kernel(
    const int*   __restrict__ chars,       // [NW, CC]
    const int*   __restrict__ chars_mask,  // [NW, CC]
    const int*   __restrict__ data_mask,   // [NW]
    const float* __restrict__ bhh_fw,      // [G3]
    const float* __restrict__ bhh_bw,
    float*       __restrict__ out)         // [NW, 512]
{
    __shared__ float hsm[HH * HROW];       // h[k][word], 20KB

    const int tid = threadIdx.x;
    const int d   = blockIdx.y;
    const int n0  = blockIdx.x * WPB;

    // weight table for this direction, viewed as u64 pairs:
    // Wd2[(k2*3 + g)*256 + tid] = ((w,w),(w',w')) for k = 2k2, 2k2+1
    const ulonglong2* __restrict__ Wd2 =
        reinterpret_cast<const ulonglong2*>(&g_Wd[d][0][0][0]);
    const float bn = (d ? bhh_bw : bhh_fw)[tid + 512];  // n-gate bias

    // init h = 0
#pragma unroll
    for (int q = 0; q < HH * HROW / 256; q++)           // 20 stores/thread
        hsm[tid + q * 256] = 0.f;
    __syncthreads();

    for (int step = 0; step < CC; step++) {
        const int t = d ? (CC - 1 - step) : step;

        // accumulators: 8 word-pairs x 3 gates, packed fp32x2
        u64 accr[WPB / 2], accz[WPB / 2], accn[WPB / 2];
#pragma unroll
        for (int p = 0; p < WPB / 2; p++) { accr[p] = 0ull; accz[p] = 0ull; accn[p] = 0ull; }

        // ---- gh = h @ W_hh^T; 2 k per iter, weights prefetched 1 iter ahead
        ulonglong2 c0 = __ldg(Wd2 + 0 * 256 + tid);
        ulonglong2 c1 = __ldg(Wd2 + 1 * 256 + tid);
        ulonglong2 c2 = __ldg(Wd2 + 2 * 256 + tid);
#pragma unroll 2
        for (int k2 = 0; k2 < HH / 2; k2++) {
            const int kn = (k2 + 1 < HH / 2) ? (k2 + 1) : k2;
            ulonglong2 p0 = __ldg(Wd2 + (kn * 3 + 0) * 256 + tid);
            ulonglong2 p1 = __ldg(Wd2 + (kn * 3 + 1) * 256 + tid);
            ulonglong2 p2 = __ldg(Wd2 + (kn * 3 + 2) * 256 + tid);
            {   // k even = 2*k2
                const ulonglong2* __restrict__ hk =
                    reinterpret_cast<const ulonglong2*>(&hsm[(2 * k2) * HROW]);
#pragma unroll
                for (int q = 0; q < WPB / 4; q++) {      // 4 LDS.128 broadcast
                    ulonglong2 a = hk[q];                // words 4q..4q+3
                    fma2(accr[2 * q],     a.x, c0.x);
                    fma2(accz[2 * q],     a.x, c1.x);
                    fma2(accn[2 * q],     a.x, c2.x);
                    fma2(accr[2 * q + 1], a.y, c0.x);
                    fma2(accz[2 * q + 1], a.y, c1.x);
                    fma2(accn[2 * q + 1], a.y, c2.x);
                }
            }
            {   // k odd = 2*k2 + 1
                const ulonglong2* __restrict__ hk =
                    reinterpret_cast<const ulonglong2*>(&hsm[(2 * k2 + 1) * HROW]);
#pragma unroll
                for (int q = 0; q < WPB / 4; q++) {
                    ulonglong2 a = hk[q];
                    fma2(accr[2 * q],     a.x, c0.y);
                    fma2(accz[2 * q],     a.x, c1.y);
                    fma2(accn[2 * q],     a.x, c2.y);
                    fma2(accr[2 * q + 1], a.y, c0.y);
                    fma2(accz[2 * q + 1], a.y, c1.y);
                    fma2(accn[2 * q + 1], a.y, c2.y);
                }
            }
            c0 = p0; c1 = p1; c2 = p2;
        }

        // ---- gates (thread-local), update h --------------------------------
        __syncthreads();                                 // all h reads done
        const float* ar = reinterpret_cast<const float*>(accr);
        const float* az = reinterpret_cast<const float*>(accz);
        const float* an = reinterpret_cast<const float*>(accn);
#pragma unroll
        for (int w = 0; w < WPB; w++) {
            const int n  = n0 + w;
            const int ch = chars[n * CC + t];
            const int mk = chars_mask[n * CC + t];
            const float* __restrict__ Prow = &g_P[d][ch][0];
            float xr = Prow[tid];                        // b_ih + b_hh folded
            float xz = Prow[tid + 256];
            float xn = Prow[tid + 512];                  // b_ih only
            float hold = hsm[tid * HROW + w];
            float r  = sigmoid_f(xr + ar[w]);
            float z  = sigmoid_f(xz + az[w]);
            float hn = bn + an[w];
            float nn = tanh_f(fmaf(r, hn, xn));
            float hnew = (1.f - z) * nn + z * hold;
            hsm[tid * HROW + w] = mk ? hnew : hold;      // freeze past seq end
        }
        __syncthreads();                                 // h visible next step
    }

    // ---- final write: out[n, d*256 + i] = h * data_mask[n] -----------------
#pragma unroll
    for (int w = 0; w < WPB; w++) {
        const int n = n0 + w;
        const float dm = data_mask[n] ? 1.f : 0.f;
        out[(size_t)n * 512 + d * 256 + tid] = hsm[tid * HROW + w] * dm;
    }
}

// ---------------------------------------------------------------------------
extern "C" void kernel_launch(void* const* d_in, const int* in_sizes, int n_in,
                              void* d_out, int out_size)
{
    const int*   chars      = (const int*)  d_in[0];
    const int*   chars_mask = (const int*)  d_in[1];
    const int*   data_mask  = (const int*)  d_in[2];
    const float* embed      = (const float*)d_in[3];
    const float* Wih_fw     = (const float*)d_in[4];
    const float* Whh_fw     = (const float*)d_in[5];
    const float* bih_fw     = (const float*)d_in[6];
    const float* bhh_fw     = (const float*)d_in[7];
    const float* Wih_bw     = (const float*)d_in[8];
    const float* Whh_bw     = (const float*)d_in[9];
    const float* bih_bw     = (const float*)d_in[10];
    const float* bhh_bw     = (const float*)d_in[11];
    float* out = (float*)d_out;

    prep_tr_kernel<<<dim3(G3, 2), HH>>>(Whh_fw, Whh_bw, Wih_fw, Wih_bw);
    prep_wd_kernel<<<dim3(HH / 2, 2), 256>>>();
    prep_p_kernel<<<dim3(NV, 2), 256>>>(embed, bih_fw, bhh_fw, bih_bw, bhh_bw);
    gru_kernel<<<dim3(BLOCKS_PER_DIR, 2), 256>>>(chars, chars_mask, data_mask,
                                                 bhh_fw, bhh_bw, out);
}

// round 7
// speedup vs baseline: 1.0017x; 1.0017x over previous
#include <cuda_runtime.h>
#include <cstdint>

// Problem constants
#define NB   32
#define NS   128
#define NW   4096      // NB*NS independent words
#define CC   32        // chars per word (time steps)
#define HH   256       // hidden
#define G3   768       // 3*H
#define EE   128       // embed dim
#define NV   262       // vocab
#define WPB  16        // words per block
#define HROW 20        // padded smem row for h (16 words + pad, 16B aligned)
#define BLOCKS_PER_DIR (NW / WPB)   // 256

typedef unsigned long long u64;

// Precomputed x-projection table: P[d][v][j] = embed[v].W_ih[d][j] + b_ih[d][j]
// (+ b_hh[j] folded in for the r and z gates, j < 512)
__device__ float g_P[2][NV][G3];
// k-major transposed recurrent weights: g_Wt[d][k][j] = W_hh[d][j][k]
__device__ float g_Wt[2][HH][G3];
// k-major transposed input weights (for coalesced prep_p)
__device__ float g_WtI[2][EE][G3];
// lane-duplicated, k-paired recurrent weights for the f32x2 hot loop:
// g_Wd[d][k2][g][j] = (w, w, w', w') with w = W_hh[g*256+j][2*k2], w' = [2*k2+1]
__device__ float4 g_Wd[2][HH / 2][3][256];

// ---------------------------------------------------------------------------
// Packed fp32x2 helpers (Blackwell 2x-rate fp32; ptxas never auto-emits)
// ---------------------------------------------------------------------------
__device__ __forceinline__ void fma2(u64& d, u64 a, u64 b) {
    asm("fma.rn.f32x2 %0, %1, %2, %3;" : "=l"(d) : "l"(a), "l"(b), "l"(d));
}

// ---------------------------------------------------------------------------
// Prepack 0: transpose W_hh (768x256) and W_ih (768x128) to k-major.
// ---------------------------------------------------------------------------
__global__ void prep_tr_kernel(const float* __restrict__ Whh_fw,
                               const float* __restrict__ Whh_bw,
                               const float* __restrict__ Wih_fw,
                               const float* __restrict__ Wih_bw)
{
    int j = blockIdx.x;
    int d = blockIdx.y;
    int k = threadIdx.x;
    const float* Wh = d ? Whh_bw : Whh_fw;
    const float* Wi = d ? Wih_bw : Wih_fw;
    g_Wt[d][k][j] = Wh[(size_t)j * HH + k];
    if (k < EE) g_WtI[d][k][j] = Wi[(size_t)j * EE + k];
}

// ---------------------------------------------------------------------------
// Prepack 1: lane-duplicated k-paired weight table (from g_Wt, coalesced).
// grid (HH/2, 2), 256 threads.
// ---------------------------------------------------------------------------
__global__ void prep_wd_kernel()
{
    int k2  = blockIdx.x;
    int d   = blockIdx.y;
    int tid = threadIdx.x;
#pragma unroll
    for (int g = 0; g < 3; g++) {
        float a = g_Wt[d][2 * k2][g * 256 + tid];
        float b = g_Wt[d][2 * k2 + 1][g * 256 + tid];
        g_Wd[d][k2][g][tid] = make_float4(a, a, b, b);
    }
}

// ---------------------------------------------------------------------------
// Prepack 2: input-projection table, coalesced via g_WtI.  grid (NV, 2).
// ---------------------------------------------------------------------------
__global__ void prep_p_kernel(const float* __restrict__ embed,
                              const float* __restrict__ bih_fw,
                              const float* __restrict__ bhh_fw,
                              const float* __restrict__ bih_bw,
                              const float* __restrict__ bhh_bw)
{
    int v = blockIdx.x;
    int d = blockIdx.y;
    int tid = threadIdx.x;
    const float* bi = d ? bih_bw : bih_fw;
    const float* bh = d ? bhh_bw : bhh_fw;
    const float* ev = embed + (size_t)v * EE;
    float a0 = 0.f, a1 = 0.f, a2 = 0.f;
#pragma unroll 4
    for (int k = 0; k < EE; k++) {
        float e = __ldg(ev + k);                        // warp-broadcast
        const float* w = &g_WtI[d][k][0];
        a0 = fmaf(e, __ldg(w + tid),       a0);
        a1 = fmaf(e, __ldg(w + tid + 256), a1);
        a2 = fmaf(e, __ldg(w + tid + 512), a2);
    }
    g_P[d][v][tid]       = a0 + bi[tid]       + bh[tid];
    g_P[d][v][tid + 256] = a1 + bi[tid + 256] + bh[tid + 256];
    g_P[d][v][tid + 512] = a2 + bi[tid + 512];          // n-gate: b_hh NOT folded
}

// ---------------------------------------------------------------------------
// Activations
// ---------------------------------------------------------------------------
__device__ __forceinline__ float sigmoid_f(float x) {
    return __fdividef(1.f, 1.f + __expf(-x));
}
__device__ __forceinline__ float tanh_f(float x) {
    x = fmaxf(-15.f, fminf(15.f, x));
    float e = __expf(-2.f * x);
    return __fdividef(1.f - e, 1.f + e);
}

// ---------------------------------------------------------------------------
// Main recurrent kernel (packed fp32x2, pre-duplicated weights).
// Block = 16 words x one direction, 256 threads; thread tid owns the (r,z,n)
// gate triple for hidden index i = tid.  Words packed in pairs into the
// f32x2 lanes; h stored word-major per k (hsm[k][word], row padded to 20)
// so one broadcast LDS.128 feeds two word-pair FFMA2s.  Weights come from
// the pre-duplicated table: one LDG.128 = two ready f32x2 operands (no dup
// movs, 6 LDG.128 per 4k vs 12 LDG.32 + 12 movs before).
// ---------------------------------------------------------------------------
__global__ void __launch_bounds__(256, 2) gru_kernel(
    const int*   __restrict__ chars,       // [NW, CC]
    const int*   __restrict__ chars_mask,  // [NW, CC]
    const int*   __restrict__ data_mask,   // [NW]
    const float* __restrict__ bhh_fw,      // [G3]
    const float* __restrict__ bhh_bw,
    float*       __restrict__ out)         // [NW, 512]
{
    __shared__ float hsm[HH * HROW];       // h[k][word], 20KB

    const int tid = threadIdx.x;
    const int d   = blockIdx.y;
    const int n0  = blockIdx.x * WPB;

    // weight table for this direction, viewed as u64 pairs:
    // Wd2[(k2*3 + g)*256 + tid] = ((w,w),(w',w')) for k = 2k2, 2k2+1
    const ulonglong2* __restrict__ Wd2 =
        reinterpret_cast<const ulonglong2*>(&g_Wd[d][0][0][0]);
    const float bn = (d ? bhh_bw : bhh_fw)[tid + 512];  // n-gate bias

    // init h = 0
#pragma unroll
    for (int q = 0; q < HH * HROW / 256; q++)           // 20 stores/thread
        hsm[tid + q * 256] = 0.f;
    __syncthreads();

    for (int step = 0; step < CC; step++) {
        const int t = d ? (CC - 1 - step) : step;

        // accumulators: 8 word-pairs x 3 gates, packed fp32x2
        u64 accr[WPB / 2], accz[WPB / 2], accn[WPB / 2];
#pragma unroll
        for (int p = 0; p < WPB / 2; p++) { accr[p] = 0ull; accz[p] = 0ull; accn[p] = 0ull; }

        // ---- gh = h @ W_hh^T; 2 k per iter, weights prefetched 1 iter ahead
        ulonglong2 c0 = __ldg(Wd2 + 0 * 256 + tid);
        ulonglong2 c1 = __ldg(Wd2 + 1 * 256 + tid);
        ulonglong2 c2 = __ldg(Wd2 + 2 * 256 + tid);
#pragma unroll 2
        for (int k2 = 0; k2 < HH / 2; k2++) {
            const int kn = (k2 + 1 < HH / 2) ? (k2 + 1) : k2;
            ulonglong2 p0 = __ldg(Wd2 + (kn * 3 + 0) * 256 + tid);
            ulonglong2 p1 = __ldg(Wd2 + (kn * 3 + 1) * 256 + tid);
            ulonglong2 p2 = __ldg(Wd2 + (kn * 3 + 2) * 256 + tid);
            {   // k even = 2*k2
                const ulonglong2* __restrict__ hk =
                    reinterpret_cast<const ulonglong2*>(&hsm[(2 * k2) * HROW]);
#pragma unroll
                for (int q = 0; q < WPB / 4; q++) {      // 4 LDS.128 broadcast
                    ulonglong2 a = hk[q];                // words 4q..4q+3
                    fma2(accr[2 * q],     a.x, c0.x);
                    fma2(accz[2 * q],     a.x, c1.x);
                    fma2(accn[2 * q],     a.x, c2.x);
                    fma2(accr[2 * q + 1], a.y, c0.x);
                    fma2(accz[2 * q + 1], a.y, c1.x);
                    fma2(accn[2 * q + 1], a.y, c2.x);
                }
            }
            {   // k odd = 2*k2 + 1
                const ulonglong2* __restrict__ hk =
                    reinterpret_cast<const ulonglong2*>(&hsm[(2 * k2 + 1) * HROW]);
#pragma unroll
                for (int q = 0; q < WPB / 4; q++) {
                    ulonglong2 a = hk[q];
                    fma2(accr[2 * q],     a.x, c0.y);
                    fma2(accz[2 * q],     a.x, c1.y);
                    fma2(accn[2 * q],     a.x, c2.y);
                    fma2(accr[2 * q + 1], a.y, c0.y);
                    fma2(accz[2 * q + 1], a.y, c1.y);
                    fma2(accn[2 * q + 1], a.y, c2.y);
                }
            }
            c0 = p0; c1 = p1; c2 = p2;
        }

        // ---- gates (thread-local), update h --------------------------------
        __syncthreads();                                 // all h reads done
        const float* ar = reinterpret_cast<const float*>(accr);
        const float* az = reinterpret_cast<const float*>(accz);
        const float* an = reinterpret_cast<const float*>(accn);
#pragma unroll
        for (int w = 0; w < WPB; w++) {
            const int n  = n0 + w;
            const int ch = chars[n * CC + t];
            const int mk = chars_mask[n * CC + t];
            const float* __restrict__ Prow = &g_P[d][ch][0];
            float xr = Prow[tid];                        // b_ih + b_hh folded
            float xz = Prow[tid + 256];
            float xn = Prow[tid + 512];                  // b_ih only
            float hold = hsm[tid * HROW + w];
            float r  = sigmoid_f(xr + ar[w]);
            float z  = sigmoid_f(xz + az[w]);
            float hn = bn + an[w];
            float nn = tanh_f(fmaf(r, hn, xn));
            float hnew = (1.f - z) * nn + z * hold;
            hsm[tid * HROW + w] = mk ? hnew : hold;      // freeze past seq end
        }
        __syncthreads();                                 // h visible next step
    }

    // ---- final write: out[n, d*256 + i] = h * data_mask[n] -----------------
#pragma unroll
    for (int w = 0; w < WPB; w++) {
        const int n = n0 + w;
        const float dm = data_mask[n] ? 1.f : 0.f;
        out[(size_t)n * 512 + d * 256 + tid] = hsm[tid * HROW + w] * dm;
    }
}

// ---------------------------------------------------------------------------
extern "C" void kernel_launch(void* const* d_in, const int* in_sizes, int n_in,
                              void* d_out, int out_size)
{
    const int*   chars      = (const int*)  d_in[0];
    const int*   chars_mask = (const int*)  d_in[1];
    const int*   data_mask  = (const int*)  d_in[2];
    const float* embed      = (const float*)d_in[3];
    const float* Wih_fw     = (const float*)d_in[4];
    const float* Whh_fw     = (const float*)d_in[5];
    const float* bih_fw     = (const float*)d_in[6];
    const float* bhh_fw     = (const float*)d_in[7];
    const float* Wih_bw     = (const float*)d_in[8];
    const float* Whh_bw     = (const float*)d_in[9];
    const float* bih_bw     = (const float*)d_in[10];
    const float* bhh_bw     = (const float*)d_in[11];
    float* out = (float*)d_out;

    prep_tr_kernel<<<dim3(G3, 2), HH>>>(Whh_fw, Whh_bw, Wih_fw, Wih_bw);
    prep_wd_kernel<<<dim3(HH / 2, 2), 256>>>();
    prep_p_kernel<<<dim3(NV, 2), 256>>>(embed, bih_fw, bhh_fw, bih_bw, bhh_bw);
    gru_kernel<<<dim3(BLOCKS_PER_DIR, 2), 256>>>(chars, chars_mask, data_mask,
                                                 bhh_fw, bhh_bw, out);
}